// round 6
// baseline (speedup 1.0000x reference)
#include <cuda_runtime.h>
#include <cstdint>

#define Bb 64
#define Nn 64
#define KDIM 512
#define NOUT 480           // NT*SEM = 30*16
#define NT 30
#define ROWS 4096
#define NSPAN 2016
#define NP1 65

// Scratch — __device__ globals (no allocation allowed)
__device__ float g_h[ROWS * NOUT];            // 7.86 MB
__device__ float g_prefix[Bb * NP1 * NOUT];   // 7.99 MB

// ---------------------------------------------------------------------------
// Kernel 1: fused gather + GEMM  h = emb[x] @ w_out^T + b_out
// BM=64, BN=96, BK=16, 192 threads. 8m(4 pairs) x 4n FFMA2 thread tile.
// 2-stage double-buffered smem, ONE barrier per k-tile; global loads for
// tile kt+2 issue before compute of kt -> latency fully hidden.
// ---------------------------------------------------------------------------
#define BM 64
#define BN 96
#define BK 16
#define GTH 192
#define ASTRIDE 68
#define NKT (KDIM / BK)    // 32

__global__ __launch_bounds__(GTH) void gemm_kernel(
    const int* __restrict__ x, const float* __restrict__ emb,
    const float* __restrict__ w, const float* __restrict__ bo)
{
    __shared__ __align__(16) float As[2][BK][ASTRIDE];   // k-major: As[st][k][m]
    __shared__ __align__(16) float Ws[2][BK][BN];        // k-major: Ws[st][k][n]
    __shared__ int rowidx[BM];

    const int tid = threadIdx.x;
    const int m0 = blockIdx.x * BM;
    const int n0 = blockIdx.y * BN;

    if (tid < BM) rowidx[tid] = x[m0 + tid];
    __syncthreads();

    const int tx = tid % 24;   // n group: cols tx*4
    const int ty = tid / 24;   // m group: rows ty*8 (4 pairs)

    // A loader: idx0 = tid (always), idx1 = tid+192 (valid for tid<64)
    const int am  = tid >> 2,          akq  = tid & 3;
    const int am2 = (tid + GTH) >> 2,  akq2 = (tid + GTH) & 3;
    const bool a2 = (tid < 64);
    const float* aptr0 = emb + (size_t)rowidx[am] * KDIM + akq * 4;
    const float* aptr1 = emb + (size_t)rowidx[a2 ? am2 : am] * KDIM + (a2 ? akq2 : akq) * 4;
    // W loader: row tid%96, kq pair (tid/96)*2
    const int wrow = tid % 96;
    const int wk0 = (tid / 96) * 2;
    const float* wptr = w + (size_t)(n0 + wrow) * KDIM + wk0 * 4;

    float4 av0, av1, wv0, wv1;

#define FETCH(KT)                                            \
    do {                                                     \
        av0 = *(const float4*)(aptr0 + (KT) * BK);           \
        av1 = *(const float4*)(aptr1 + (KT) * BK);           \
        wv0 = *(const float4*)(wptr + (KT) * BK);            \
        wv1 = *(const float4*)(wptr + (KT) * BK + 4);        \
    } while (0)

#define STORE(ST)                                            \
    do {                                                     \
        As[ST][akq * 4 + 0][am] = av0.x;                     \
        As[ST][akq * 4 + 1][am] = av0.y;                     \
        As[ST][akq * 4 + 2][am] = av0.z;                     \
        As[ST][akq * 4 + 3][am] = av0.w;                     \
        if (a2) {                                            \
            As[ST][akq2 * 4 + 0][am2] = av1.x;               \
            As[ST][akq2 * 4 + 1][am2] = av1.y;               \
            As[ST][akq2 * 4 + 2][am2] = av1.z;               \
            As[ST][akq2 * 4 + 3][am2] = av1.w;               \
        }                                                    \
        Ws[ST][wk0 * 4 + 0][wrow] = wv0.x;                   \
        Ws[ST][wk0 * 4 + 1][wrow] = wv0.y;                   \
        Ws[ST][wk0 * 4 + 2][wrow] = wv0.z;                   \
        Ws[ST][wk0 * 4 + 3][wrow] = wv0.w;                   \
        Ws[ST][wk0 * 4 + 4][wrow] = wv1.x;                   \
        Ws[ST][wk0 * 4 + 5][wrow] = wv1.y;                   \
        Ws[ST][wk0 * 4 + 6][wrow] = wv1.z;                   \
        Ws[ST][wk0 * 4 + 7][wrow] = wv1.w;                   \
    } while (0)

    unsigned long long acc[4][4];
#pragma unroll
    for (int p = 0; p < 4; p++)
#pragma unroll
        for (int j = 0; j < 4; j++) acc[p][j] = 0ull;

#define COMPUTE(ST)                                                          \
    do {                                                                     \
        _Pragma("unroll")                                                    \
        for (int k = 0; k < BK; k++) {                                       \
            const ulonglong2* ap = (const ulonglong2*)&As[ST][k][ty * 8];    \
            const ulonglong2 a01 = ap[0];                                    \
            const ulonglong2 a23 = ap[1];                                    \
            unsigned long long a[4] = {a01.x, a01.y, a23.x, a23.y};          \
            const uint4 bu = *(const uint4*)&Ws[ST][k][tx * 4];              \
            unsigned long long bd[4];                                        \
            asm("mov.b64 %0, {%1, %1};" : "=l"(bd[0]) : "r"(bu.x));          \
            asm("mov.b64 %0, {%1, %1};" : "=l"(bd[1]) : "r"(bu.y));          \
            asm("mov.b64 %0, {%1, %1};" : "=l"(bd[2]) : "r"(bu.z));          \
            asm("mov.b64 %0, {%1, %1};" : "=l"(bd[3]) : "r"(bu.w));          \
            _Pragma("unroll")                                                \
            for (int p = 0; p < 4; p++)                                      \
                _Pragma("unroll")                                            \
                for (int j = 0; j < 4; j++)                                  \
                    asm("fma.rn.f32x2 %0, %1, %2, %0;"                       \
                        : "+l"(acc[p][j]) : "l"(a[p]), "l"(bd[j]));          \
        }                                                                    \
    } while (0)

    // Prologue: stage 0 filled with tile 0; regs fetch tile 1.
    FETCH(0);
    STORE(0);
    FETCH(1);
    __syncthreads();

    // Steady state: at entry of kt, regs hold data(kt+1), smem[kt&1] holds kt.
#pragma unroll 1
    for (int kt = 0; kt < NKT - 1; kt++) {
        STORE((kt + 1) & 1);           // stage last read at compute(kt-1); barrier separates
        if (kt < NKT - 2) FETCH(kt + 2);
        COMPUTE(kt & 1);
        __syncthreads();
    }
    COMPUTE((NKT - 1) & 1);

    // Epilogue: unpack pairs, add bias, store
    const float4 bb = *(const float4*)(bo + n0 + tx * 4);
#pragma unroll
    for (int p = 0; p < 4; p++) {
        unsigned lo[4], hi[4];
#pragma unroll
        for (int j = 0; j < 4; j++)
            asm("mov.b64 {%0, %1}, %2;" : "=r"(lo[j]), "=r"(hi[j]) : "l"(acc[p][j]));
        const int row0 = m0 + ty * 8 + 2 * p;
        float4 o0, o1;
        o0.x = __uint_as_float(lo[0]) + bb.x;
        o0.y = __uint_as_float(lo[1]) + bb.y;
        o0.z = __uint_as_float(lo[2]) + bb.z;
        o0.w = __uint_as_float(lo[3]) + bb.w;
        o1.x = __uint_as_float(hi[0]) + bb.x;
        o1.y = __uint_as_float(hi[1]) + bb.y;
        o1.z = __uint_as_float(hi[2]) + bb.z;
        o1.w = __uint_as_float(hi[3]) + bb.w;
        *(float4*)(g_h + (size_t)row0 * NOUT + n0 + tx * 4) = o0;
        *(float4*)(g_h + (size_t)(row0 + 1) * NOUT + n0 + tx * 4) = o1;
    }
}

// ---------------------------------------------------------------------------
// Kernel 2: masked cumsum over sequence -> prefix [B, N+1, 480]
// ---------------------------------------------------------------------------
__global__ __launch_bounds__(120) void prefix_kernel(const int* __restrict__ lengths)
{
    const int b = blockIdx.y;
    const int o = blockIdx.x * 120 + threadIdx.x;
    const int len = lengths[b];
    float acc = 0.0f;
    g_prefix[((size_t)b * NP1 + 0) * NOUT + o] = 0.0f;
#pragma unroll 8
    for (int n = 0; n < Nn; n++) {
        const float v = g_h[((size_t)b * Nn + n) * NOUT + o];
        if (n < len) acc += v;
        g_prefix[((size_t)b * NP1 + n + 1) * NOUT + o] = acc;
    }
}

// ---------------------------------------------------------------------------
// Kernel 3: span features + L2 norm, smem-tiled over 8x8 (l, r) tiles.
// ---------------------------------------------------------------------------
#define STH 256

__global__ __launch_bounds__(STH) void span_kernel(float* __restrict__ out)
{
    __shared__ float sL[8][NOUT];
    __shared__ float sR[8][NOUT];

    const int b = blockIdx.y;
    const int t = blockIdx.x;                 // 0..35, t = rt*(rt+1)/2 + lt
    int rt = 0;
    while ((rt + 1) * (rt + 2) / 2 <= t) rt++;
    const int lt = t - rt * (rt + 1) / 2;

    const int tid = threadIdx.x;
    const float* pb = g_prefix + (size_t)b * NP1 * NOUT;

    for (int i4 = tid; i4 < 16 * (NOUT / 4); i4 += STH) {
        const int row = i4 / (NOUT / 4);
        const int pos = i4 % (NOUT / 4);
        const int grow = (row < 8) ? (lt * 8 + row) : (rt * 8 + (row - 8) + 1);
        const float4 v = *(const float4*)(pb + (size_t)grow * NOUT + pos * 4);
        if (row < 8) *(float4*)&sL[row][pos * 4] = v;
        else         *(float4*)&sR[row - 8][pos * 4] = v;
    }
    __syncthreads();

    const int slot = tid / 60;        // 0..3 active, 4 = spare
    const int lane = tid % 60;
    const int base = (slot < 4) ? slot : 0;
    const bool diag = (lt == rt);

#pragma unroll 4
    for (int i = 0; i < 16; i++) {
        const int sp = base + 4 * i;          // 0..63
        const int li = sp & 7;
        const int ri = sp >> 3;

        const float4* Rp = (const float4*)&sR[ri][0];
        const float4* Lp = (const float4*)&sL[li][0];
        const float4 ra = Rp[lane],      la = Lp[lane];
        const float4 rb = Rp[60 + lane], lb = Lp[60 + lane];

        float4 da, db;
        da.x = ra.x - la.x; da.y = ra.y - la.y; da.z = ra.z - la.z; da.w = ra.w - la.w;
        db.x = rb.x - lb.x; db.y = rb.y - lb.y; db.z = rb.z - lb.z; db.w = rb.w - lb.w;

        float sqA = da.x * da.x;
        sqA = fmaf(da.y, da.y, sqA); sqA = fmaf(da.z, da.z, sqA); sqA = fmaf(da.w, da.w, sqA);
        float sqB = db.x * db.x;
        sqB = fmaf(db.y, db.y, sqB); sqB = fmaf(db.z, db.z, sqB); sqB = fmaf(db.w, db.w, sqB);

        sqA += __shfl_xor_sync(0xffffffffu, sqA, 1);
        sqA += __shfl_xor_sync(0xffffffffu, sqA, 2);
        sqB += __shfl_xor_sync(0xffffffffu, sqB, 1);
        sqB += __shfl_xor_sync(0xffffffffu, sqB, 2);

        const float invA = rsqrtf(sqA);
        const float invB = rsqrtf(sqB);

        if (slot < 4 && (!diag || li < ri)) {
            const int l = lt * 8 + li;
            const int r = rt * 8 + ri;
            const int k = r - l;
            const int s = (((k - 1) * (128 - k)) >> 1) + l;
            float* op = out + (size_t)(b * NSPAN + s) * NOUT;
            float4 oa, ob;
            oa.x = da.x * invA; oa.y = da.y * invA; oa.z = da.z * invA; oa.w = da.w * invA;
            ob.x = db.x * invB; ob.y = db.y * invB; ob.z = db.z * invB; ob.w = db.w * invB;
            *(float4*)(op + lane * 4) = oa;
            *(float4*)(op + 240 + lane * 4) = ob;
        }
    }
}

// ---------------------------------------------------------------------------
extern "C" void kernel_launch(void* const* d_in, const int* in_sizes, int n_in,
                              void* d_out, int out_size)
{
    const int*   x       = (const int*)d_in[0];
    const int*   lengths = (const int*)d_in[1];
    const float* emb     = (const float*)d_in[2];
    const float* w_out   = (const float*)d_in[3];
    const float* b_out   = (const float*)d_in[4];
    float* out = (float*)d_out;

    gemm_kernel<<<dim3(ROWS / BM, NOUT / BN), GTH>>>(x, emb, w_out, b_out);
    prefix_kernel<<<dim3(4, Bb), 120>>>(lengths);
    span_kernel<<<dim3(36, Bb), STH>>>(out);
}